// round 3
// baseline (speedup 1.0000x reference)
#include <cuda_runtime.h>
#include <cstdint>

#define N_PTS   4096
#define DIM     128
#define TOPK    4

// ---------------- Z = x @ W  (precomputed, 8192x128 @ 128x128) ----------------
__device__ float Z_buf[2 * N_PTS * DIM];   // 4 MB scratch

#define GA_THREADS 256
#define GA_ROWS    32          // rows per block; 8 warps x 4 rows

__global__ void __launch_bounds__(GA_THREADS, 2)
gemm_xw(const float* __restrict__ x, const float* __restrict__ W)
{
    extern __shared__ float smemA[];
    float4* W_s = (float4*)smemA;             // 128*32 float4 = 64 KB  (W[d][o])
    float*  x_s = (float*)(W_s + DIM * 32);   // 32*128 floats = 16 KB

    const int tid = threadIdx.x;
    const int g0  = blockIdx.x * GA_ROWS;

    const float4* W4 = (const float4*)W;
    #pragma unroll
    for (int i = tid; i < DIM * 32; i += GA_THREADS) W_s[i] = W4[i];

    const float4* xg = (const float4*)x + (size_t)g0 * 32;
    float4* xs4 = (float4*)x_s;
    #pragma unroll
    for (int i = tid; i < GA_ROWS * 32; i += GA_THREADS) xs4[i] = xg[i];
    __syncthreads();

    const int warp = tid >> 5;
    const int lane = tid & 31;
    const float* xr = x_s + warp * 4 * DIM;   // 4 rows per warp

    float4 a0 = make_float4(0.f,0.f,0.f,0.f);
    float4 a1 = a0, a2 = a0, a3 = a0;

    #pragma unroll 4
    for (int d = 0; d < DIM; d++) {
        float4 wv = W_s[d * 32 + lane];
        float y0 = xr[d];
        float y1 = xr[d + DIM];
        float y2 = xr[d + 2*DIM];
        float y3 = xr[d + 3*DIM];
        a0.x = fmaf(y0, wv.x, a0.x); a0.y = fmaf(y0, wv.y, a0.y);
        a0.z = fmaf(y0, wv.z, a0.z); a0.w = fmaf(y0, wv.w, a0.w);
        a1.x = fmaf(y1, wv.x, a1.x); a1.y = fmaf(y1, wv.y, a1.y);
        a1.z = fmaf(y1, wv.z, a1.z); a1.w = fmaf(y1, wv.w, a1.w);
        a2.x = fmaf(y2, wv.x, a2.x); a2.y = fmaf(y2, wv.y, a2.y);
        a2.z = fmaf(y2, wv.z, a2.z); a2.w = fmaf(y2, wv.w, a2.w);
        a3.x = fmaf(y3, wv.x, a3.x); a3.y = fmaf(y3, wv.y, a3.y);
        a3.z = fmaf(y3, wv.z, a3.z); a3.w = fmaf(y3, wv.w, a3.w);
    }

    float4* Z4 = (float4*)Z_buf;
    const size_t r = (size_t)g0 + warp * 4;
    Z4[(r + 0) * 32 + lane] = a0;
    Z4[(r + 1) * 32 + lane] = a1;
    Z4[(r + 2) * 32 + lane] = a2;
    Z4[(r + 3) * 32 + lane] = a3;
}

// --------- top-4 neighbor scan (dot-score, top-5 margin) + exact rerank ----------
#define GB_THREADS 256
#define GB_WARPS   8
#define RPW        4                       // rows per warp
#define GB_ROWS    (GB_WARPS * RPW)        // 32 rows per block

struct Top5 { float s0,s1,s2,s3,s4; int j0,j1,j2,j3,j4; };

__device__ __forceinline__ void ins5(Top5& T, float t, int j)
{   // caller guarantees t > T.s4
    T.s4 = t; T.j4 = j;
    if (t > T.s3) { T.s4=T.s3; T.j4=T.j3; T.s3=t; T.j3=j;
      if (t > T.s2) { T.s3=T.s2; T.j3=T.j2; T.s2=t; T.j2=j;
        if (t > T.s1) { T.s2=T.s1; T.j2=T.j1; T.s1=t; T.j1=j;
          if (t > T.s0) { T.s1=T.s0; T.j1=T.j0; T.s0=t; T.j0=j; } } } }
}

__device__ __forceinline__ unsigned long long exkey(const float4* __restrict__ pos_s,
                                                    float4 P, int j)
{   // exact difference-form squared distance, packed with index (d2>=0)
    float4 q = pos_s[j];
    float dx = P.x - q.x, dy = P.y - q.y, dz = P.z - q.z;
    float d2 = fmaf(dz, dz, fmaf(dy, dy, dx * dx));
    return ((unsigned long long)__float_as_uint(d2) << 32) | (unsigned)j;
}

#define SWP(a,b) { unsigned long long _t; if (a > b) { _t = a; a = b; b = _t; } }

__device__ __forceinline__ void finish_row(const float4* __restrict__ pos_s,
                                           const float4* __restrict__ Z4,
                                           float4 bv, float4* __restrict__ out4,
                                           float4 P, const Top5& T,
                                           int lane, size_t orow)
{
    // exactify the 5 score-candidates
    unsigned long long k0 = exkey(pos_s, P, T.j0);
    unsigned long long k1 = exkey(pos_s, P, T.j1);
    unsigned long long k2 = exkey(pos_s, P, T.j2);
    unsigned long long k3 = exkey(pos_s, P, T.j3);
    unsigned long long k4 = exkey(pos_s, P, T.j4);
    // 9-comparator sorting network for 5 (ascending); keep smallest 4
    SWP(k0,k1) SWP(k3,k4) SWP(k2,k4) SWP(k2,k3) SWP(k0,k3)
    SWP(k0,k2) SWP(k1,k4) SWP(k1,k3) SWP(k1,k2)

    float w0,w1,w2,w3; int i0,i1,i2,i3;
    #pragma unroll
    for (int r = 0; r < TOPK; r++) {
        unsigned long long v = k0;
        #pragma unroll
        for (int off = 16; off; off >>= 1) {
            unsigned long long o = __shfl_xor_sync(0xffffffffu, v, off);
            v = (o < v) ? o : v;
        }
        if (k0 == v) { k0 = k1; k1 = k2; k2 = k3; k3 = ~0ull; }
        float d2 = __uint_as_float((unsigned)(v >> 32));
        int   jj = (int)(v & 0xffffffffull);
        float ww = expf(-0.5f * (d2 + 1e-8f));
        if (r == 0) { w0 = ww; i0 = jj; }
        else if (r == 1) { w1 = ww; i1 = jj; }
        else if (r == 2) { w2 = ww; i2 = jj; }
        else { w3 = ww; i3 = jj; }
    }
    float inv = 1.0f / (((w0 + w1) + w2) + w3 + 1e-8f);
    w0 *= inv; w1 *= inv; w2 *= inv; w3 *= inv;

    float4 z0 = Z4[(size_t)i0 * 32 + lane];
    float4 z1 = Z4[(size_t)i1 * 32 + lane];
    float4 z2 = Z4[(size_t)i2 * 32 + lane];
    float4 z3 = Z4[(size_t)i3 * 32 + lane];
    float4 acc = bv;
    acc.x = fmaf(w0,z0.x, fmaf(w1,z1.x, fmaf(w2,z2.x, fmaf(w3,z3.x, acc.x))));
    acc.y = fmaf(w0,z0.y, fmaf(w1,z1.y, fmaf(w2,z2.y, fmaf(w3,z3.y, acc.y))));
    acc.z = fmaf(w0,z0.z, fmaf(w1,z1.z, fmaf(w2,z2.z, fmaf(w3,z3.z, acc.z))));
    acc.w = fmaf(w0,z0.w, fmaf(w1,z1.w, fmaf(w2,z2.w, fmaf(w3,z3.w, acc.w))));
    out4[orow * 32 + lane] = acc;
}

__global__ void __launch_bounds__(GB_THREADS, 2)
topk_gather(const float* __restrict__ pos,
            const float* __restrict__ bias,
            float* __restrict__ out)
{
    extern __shared__ float4 pos_s[];          // 4096 float4 = 64 KB; .w = -0.5*|p|^2

    const int tid = threadIdx.x;
    const int g0  = blockIdx.x * GB_ROWS;
    const int b   = g0 >> 12;

    const float* pb = pos + (size_t)b * N_PTS * 3;
    for (int n = tid; n < N_PTS; n += GB_THREADS) {
        float px = pb[3*n], py = pb[3*n+1], pz = pb[3*n+2];
        float4 q;
        q.x = px; q.y = py; q.z = pz;
        q.w = -0.5f * fmaf(pz, pz, fmaf(py, py, px * px));
        pos_s[n] = q;
    }
    __syncthreads();

    const int warp = tid >> 5;
    const int lane = tid & 31;
    const int r0   = g0 + warp * RPW;
    const int n0   = r0 & (N_PTS - 1);

    const float4 P0 = pos_s[n0 + 0];
    const float4 P1 = pos_s[n0 + 1];
    const float4 P2 = pos_s[n0 + 2];
    const float4 P3 = pos_s[n0 + 3];

    const float NINF = __int_as_float(0xff800000);
    Top5 T0 = {NINF,NINF,NINF,NINF,NINF, 0,0,0,0,0};
    Top5 T1 = T0, T2 = T0, T3 = T0;

    #pragma unroll 4
    for (int j = lane; j < N_PTS; j += 32) {
        float4 q = pos_s[j];
        float t0 = fmaf(P0.x,q.x, fmaf(P0.y,q.y, fmaf(P0.z,q.z, q.w)));
        float t1 = fmaf(P1.x,q.x, fmaf(P1.y,q.y, fmaf(P1.z,q.z, q.w)));
        float t2 = fmaf(P2.x,q.x, fmaf(P2.y,q.y, fmaf(P2.z,q.z, q.w)));
        float t3 = fmaf(P3.x,q.x, fmaf(P3.y,q.y, fmaf(P3.z,q.z, q.w)));
        bool b0 = t0 > T0.s4;
        bool b1 = t1 > T1.s4;
        bool b2 = t2 > T2.s4;
        bool b3 = t3 > T3.s4;
        if (b0 | b1 | b2 | b3) {               // rarely taken
            if (b0) ins5(T0, t0, j);
            if (b1) ins5(T1, t1, j);
            if (b2) ins5(T2, t2, j);
            if (b3) ins5(T3, t3, j);
        }
    }

    const float4* Z4  = (const float4*)Z_buf + (size_t)b * N_PTS * 32;
    const float4  bv  = ((const float4*)bias)[lane];
    float4* out4 = (float4*)out;

    finish_row(pos_s, Z4, bv, out4, P0, T0, lane, (size_t)(r0 + 0));
    finish_row(pos_s, Z4, bv, out4, P1, T1, lane, (size_t)(r0 + 1));
    finish_row(pos_s, Z4, bv, out4, P2, T2, lane, (size_t)(r0 + 2));
    finish_row(pos_s, Z4, bv, out4, P3, T3, lane, (size_t)(r0 + 3));
}

extern "C" void kernel_launch(void* const* d_in, const int* in_sizes, int n_in,
                              void* d_out, int out_size)
{
    const float* x    = (const float*)d_in[0];
    const float* pos  = (const float*)d_in[1];
    const float* W    = (const float*)d_in[2];
    const float* bias = (const float*)d_in[3];
    float* out        = (float*)d_out;

    const int rows = in_sizes[1] / 3;                  // B * N = 8192

    const size_t smemA = (size_t)DIM * 32 * 16 + (size_t)GA_ROWS * DIM * 4;  // 80 KB
    cudaFuncSetAttribute(gemm_xw, cudaFuncAttributeMaxDynamicSharedMemorySize, (int)smemA);
    gemm_xw<<<rows / GA_ROWS, GA_THREADS, smemA>>>(x, W);

    const size_t smemB = (size_t)N_PTS * 16;           // 64 KB
    cudaFuncSetAttribute(topk_gather, cudaFuncAttributeMaxDynamicSharedMemorySize, (int)smemB);
    topk_gather<<<rows / GB_ROWS, GB_THREADS, smemB>>>(pos, bias, out);
}

// round 4
// speedup vs baseline: 2.1388x; 2.1388x over previous
#include <cuda_runtime.h>
#include <cstdint>

#define N_PTS   4096
#define DIM     128
#define TOPK    4

// ---------------- Z = x @ W  (precomputed, 8192x128 @ 128x128) ----------------
__device__ float Z_buf[2 * N_PTS * DIM];   // 4 MB scratch

#define GA_THREADS 256
#define GA_ROWS    32          // rows per block; 8 warps x 4 rows

__global__ void __launch_bounds__(GA_THREADS, 2)
gemm_xw(const float* __restrict__ x, const float* __restrict__ W)
{
    extern __shared__ float smemA[];
    float4* W_s = (float4*)smemA;             // 128*32 float4 = 64 KB
    float*  x_s = (float*)(W_s + DIM * 32);   // 32*128 floats = 16 KB

    const int tid = threadIdx.x;
    const int g0  = blockIdx.x * GA_ROWS;

    const float4* W4 = (const float4*)W;
    #pragma unroll
    for (int i = tid; i < DIM * 32; i += GA_THREADS) W_s[i] = W4[i];

    const float4* xg = (const float4*)x + (size_t)g0 * 32;
    float4* xs4 = (float4*)x_s;
    #pragma unroll
    for (int i = tid; i < GA_ROWS * 32; i += GA_THREADS) xs4[i] = xg[i];
    __syncthreads();

    const int warp = tid >> 5;
    const int lane = tid & 31;
    const float* xr = x_s + warp * 4 * DIM;

    float4 a0 = make_float4(0.f,0.f,0.f,0.f);
    float4 a1 = a0, a2 = a0, a3 = a0;

    #pragma unroll 4
    for (int d = 0; d < DIM; d++) {
        float4 wv = W_s[d * 32 + lane];
        float y0 = xr[d];
        float y1 = xr[d + DIM];
        float y2 = xr[d + 2*DIM];
        float y3 = xr[d + 3*DIM];
        a0.x = fmaf(y0, wv.x, a0.x); a0.y = fmaf(y0, wv.y, a0.y);
        a0.z = fmaf(y0, wv.z, a0.z); a0.w = fmaf(y0, wv.w, a0.w);
        a1.x = fmaf(y1, wv.x, a1.x); a1.y = fmaf(y1, wv.y, a1.y);
        a1.z = fmaf(y1, wv.z, a1.z); a1.w = fmaf(y1, wv.w, a1.w);
        a2.x = fmaf(y2, wv.x, a2.x); a2.y = fmaf(y2, wv.y, a2.y);
        a2.z = fmaf(y2, wv.z, a2.z); a2.w = fmaf(y2, wv.w, a2.w);
        a3.x = fmaf(y3, wv.x, a3.x); a3.y = fmaf(y3, wv.y, a3.y);
        a3.z = fmaf(y3, wv.z, a3.z); a3.w = fmaf(y3, wv.w, a3.w);
    }

    float4* Z4 = (float4*)Z_buf;
    const size_t r = (size_t)g0 + warp * 4;
    Z4[(r + 0) * 32 + lane] = a0;
    Z4[(r + 1) * 32 + lane] = a1;
    Z4[(r + 2) * 32 + lane] = a2;
    Z4[(r + 3) * 32 + lane] = a3;
}

// ---------------- row-per-lane top-4 scan + gather ----------------
// Block: 4 warps. Each block owns 32 rows (one per lane, shared by all warps).
// Warp w scans candidate slice [w*1024, (w+1)*1024), keeping per-lane top-5
// smallest packed keys (d2 with low 12 mantissa bits = candidate index).
// Merge via smem, exact difference-form rerank of 5, expf, normalize, gather Z.

#define GB_THREADS 128
#define GB_WARPS   4
#define SLICE      (N_PTS / GB_WARPS)      // 1024
#define GB_ROWS    32

__device__ __forceinline__ float packkey(float d2c, int j)
{
    return __int_as_float((__float_as_int(d2c) & 0xFFFFF000) | j);
}

#define BUBBLE5(k)                                            \
    { float _t, _k = (k);                                     \
      _t = fminf(s0, _k); _k = fmaxf(s0, _k); s0 = _t;        \
      _t = fminf(s1, _k); _k = fmaxf(s1, _k); s1 = _t;        \
      _t = fminf(s2, _k); _k = fmaxf(s2, _k); s2 = _t;        \
      _t = fminf(s3, _k); _k = fmaxf(s3, _k); s3 = _t;        \
      s4 = fminf(s4, _k); }

#define SWP(a,b) { unsigned long long _t; if (a > b) { _t = a; a = b; b = _t; } }

__global__ void __launch_bounds__(GB_THREADS, 3)
topk_gather(const float* __restrict__ pos,
            const float* __restrict__ bias,
            float* __restrict__ out)
{
    extern __shared__ float smemB[];
    float4* pos_s = (float4*)smemB;                    // [4096] .w = -0.5*|p|^2
    float*  m_s   = (float*)(pos_s + N_PTS);           // [3*32*5] merge staging
    float*  w_s   = m_s + 3 * 32 * 5;                  // [32*4] weights
    int*    idx_s = (int*)(w_s + 32 * 4);              // [32*4] indices

    const int tid  = threadIdx.x;
    const int warp = tid >> 5;
    const int lane = tid & 31;
    const int r0   = blockIdx.x * GB_ROWS;
    const int b    = r0 >> 12;
    const int n0   = r0 & (N_PTS - 1);

    // ---- load pos for this batch: 4 points per thread-iteration (3x float4) ----
    const float4* pb4 = (const float4*)(pos + (size_t)b * N_PTS * 3);
    for (int g = tid; g < N_PTS / 4; g += GB_THREADS) {
        float4 a = pb4[3*g + 0];
        float4 c = pb4[3*g + 1];
        float4 d = pb4[3*g + 2];
        float4 q;
        q.x = a.x; q.y = a.y; q.z = a.z;
        q.w = -0.5f * fmaf(q.z, q.z, fmaf(q.y, q.y, q.x * q.x));
        pos_s[4*g + 0] = q;
        q.x = a.w; q.y = c.x; q.z = c.y;
        q.w = -0.5f * fmaf(q.z, q.z, fmaf(q.y, q.y, q.x * q.x));
        pos_s[4*g + 1] = q;
        q.x = c.z; q.y = c.w; q.z = d.x;
        q.w = -0.5f * fmaf(q.z, q.z, fmaf(q.y, q.y, q.x * q.x));
        pos_s[4*g + 2] = q;
        q.x = d.y; q.y = d.z; q.z = d.w;
        q.w = -0.5f * fmaf(q.z, q.z, fmaf(q.y, q.y, q.x * q.x));
        pos_s[4*g + 3] = q;
    }
    __syncthreads();

    // ---- per-lane row state ----
    const float4 P  = pos_s[n0 + lane];
    const float  Pw2 = -2.0f * P.w;                    // |pi|^2

    const float INF = __int_as_float(0x7f800000);
    float s0 = INF, s1 = INF, s2 = INF, s3 = INF, s4 = INF;

    const int base = warp * SLICE;
    #pragma unroll 8
    for (int jj = 0; jj < SLICE; jj++) {
        const int j = base + jj;
        float4 q = pos_s[j];                           // warp-broadcast LDS.128
        float t  = fmaf(P.x, q.x, fmaf(P.y, q.y, fmaf(P.z, q.z, q.w)));
        float d2c = fmaf(-2.0f, t, Pw2);               // ~exact squared distance
        if (d2c < s4) {                                // per-lane rare
            BUBBLE5(packkey(d2c, j));
        }
    }

    // ---- merge: warps 1-3 stage their top-5, warp 0 folds them in ----
    if (warp != 0) {
        float* m = m_s + ((warp - 1) * 32 + lane) * 5;
        m[0] = s0; m[1] = s1; m[2] = s2; m[3] = s3; m[4] = s4;
    }
    __syncthreads();

    if (warp == 0) {
        #pragma unroll
        for (int w = 0; w < 3; w++) {
            const float* m = m_s + (w * 32 + lane) * 5;
            #pragma unroll
            for (int i = 0; i < 5; i++) BUBBLE5(m[i]);
        }

        // ---- exact rerank of the 5 survivors (difference-form d2, u64 keys) ----
        float cand[5] = { s0, s1, s2, s3, s4 };
        unsigned long long k[5];
        #pragma unroll
        for (int i = 0; i < 5; i++) {
            int j = __float_as_int(cand[i]) & 0xFFF;
            float4 q = pos_s[j];
            float dx = P.x - q.x, dy = P.y - q.y, dz = P.z - q.z;
            float d2 = fmaf(dz, dz, fmaf(dy, dy, dx * dx));
            k[i] = ((unsigned long long)__float_as_uint(d2) << 32) | (unsigned)j;
        }
        SWP(k[0],k[1]) SWP(k[3],k[4]) SWP(k[2],k[4]) SWP(k[2],k[3]) SWP(k[0],k[3])
        SWP(k[0],k[2]) SWP(k[1],k[4]) SWP(k[1],k[3]) SWP(k[1],k[2])

        float wgt[TOPK];
        #pragma unroll
        for (int r = 0; r < TOPK; r++) {
            float d2 = __uint_as_float((unsigned)(k[r] >> 32));
            wgt[r]   = expf(-0.5f * (d2 + 1e-8f));
            idx_s[lane * TOPK + r] = (int)(k[r] & 0xFFFFFFFFull);
        }
        float inv = 1.0f / (((wgt[0] + wgt[1]) + wgt[2]) + wgt[3] + 1e-8f);
        #pragma unroll
        for (int r = 0; r < TOPK; r++) w_s[lane * TOPK + r] = wgt[r] * inv;
    }
    __syncthreads();

    // ---- gather: each warp handles 8 rows; 32 lanes cover the 128 outputs ----
    const float4* Z4 = (const float4*)Z_buf + (size_t)b * N_PTS * 32;
    const float4  bv = ((const float4*)bias)[lane];
    float4* out4 = (float4*)out;

    #pragma unroll
    for (int rr = warp; rr < GB_ROWS; rr += GB_WARPS) {
        float w0 = w_s[rr*4+0], w1 = w_s[rr*4+1], w2 = w_s[rr*4+2], w3 = w_s[rr*4+3];
        int   i0 = idx_s[rr*4+0], i1 = idx_s[rr*4+1], i2 = idx_s[rr*4+2], i3 = idx_s[rr*4+3];
        float4 z0 = Z4[(size_t)i0 * 32 + lane];
        float4 z1 = Z4[(size_t)i1 * 32 + lane];
        float4 z2 = Z4[(size_t)i2 * 32 + lane];
        float4 z3 = Z4[(size_t)i3 * 32 + lane];
        float4 acc = bv;
        acc.x = fmaf(w0,z0.x, fmaf(w1,z1.x, fmaf(w2,z2.x, fmaf(w3,z3.x, acc.x))));
        acc.y = fmaf(w0,z0.y, fmaf(w1,z1.y, fmaf(w2,z2.y, fmaf(w3,z3.y, acc.y))));
        acc.z = fmaf(w0,z0.z, fmaf(w1,z1.z, fmaf(w2,z2.z, fmaf(w3,z3.z, acc.z))));
        acc.w = fmaf(w0,z0.w, fmaf(w1,z1.w, fmaf(w2,z2.w, fmaf(w3,z3.w, acc.w))));
        out4[(size_t)(r0 + rr) * 32 + lane] = acc;
    }
}

extern "C" void kernel_launch(void* const* d_in, const int* in_sizes, int n_in,
                              void* d_out, int out_size)
{
    const float* x    = (const float*)d_in[0];
    const float* pos  = (const float*)d_in[1];
    const float* W    = (const float*)d_in[2];
    const float* bias = (const float*)d_in[3];
    float* out        = (float*)d_out;

    const int rows = in_sizes[1] / 3;                  // B * N = 8192

    const size_t smemA = (size_t)DIM * 32 * 16 + (size_t)GA_ROWS * DIM * 4;  // 80 KB
    cudaFuncSetAttribute(gemm_xw, cudaFuncAttributeMaxDynamicSharedMemorySize, (int)smemA);
    gemm_xw<<<rows / GA_ROWS, GA_THREADS, smemA>>>(x, W);

    const size_t smemB = (size_t)N_PTS * 16            // pos_s
                       + 3 * 32 * 5 * 4                // merge staging
                       + 32 * 4 * 4                    // weights
                       + 32 * 4 * 4;                   // indices
    cudaFuncSetAttribute(topk_gather, cudaFuncAttributeMaxDynamicSharedMemorySize, (int)smemB);
    topk_gather<<<rows / GB_ROWS, GB_THREADS, smemB>>>(pos, bias, out);
}

// round 5
// speedup vs baseline: 2.6052x; 1.2180x over previous
#include <cuda_runtime.h>
#include <cstdint>

#define N_PTS   4096
#define DIM     128
#define TOPK    4

// ---------------- Z = x @ W  (precomputed, 8192x128 @ 128x128) ----------------
__device__ float Z_buf[2 * N_PTS * DIM];   // 4 MB scratch

#define GA_THREADS 256
#define GA_ROWS    32          // rows per block; 8 warps x 4 rows

__global__ void __launch_bounds__(GA_THREADS, 2)
gemm_xw(const float* __restrict__ x, const float* __restrict__ W)
{
    extern __shared__ float smemA[];
    float4* W_s = (float4*)smemA;             // 128*32 float4 = 64 KB
    float*  x_s = (float*)(W_s + DIM * 32);   // 32*128 floats = 16 KB

    const int tid = threadIdx.x;
    const int g0  = blockIdx.x * GA_ROWS;

    const float4* W4 = (const float4*)W;
    #pragma unroll
    for (int i = tid; i < DIM * 32; i += GA_THREADS) W_s[i] = W4[i];

    const float4* xg = (const float4*)x + (size_t)g0 * 32;
    float4* xs4 = (float4*)x_s;
    #pragma unroll
    for (int i = tid; i < GA_ROWS * 32; i += GA_THREADS) xs4[i] = xg[i];
    __syncthreads();

    const int warp = tid >> 5;
    const int lane = tid & 31;
    const float* xr = x_s + warp * 4 * DIM;

    float4 a0 = make_float4(0.f,0.f,0.f,0.f);
    float4 a1 = a0, a2 = a0, a3 = a0;

    #pragma unroll 4
    for (int d = 0; d < DIM; d++) {
        float4 wv = W_s[d * 32 + lane];
        float y0 = xr[d];
        float y1 = xr[d + DIM];
        float y2 = xr[d + 2*DIM];
        float y3 = xr[d + 3*DIM];
        a0.x = fmaf(y0, wv.x, a0.x); a0.y = fmaf(y0, wv.y, a0.y);
        a0.z = fmaf(y0, wv.z, a0.z); a0.w = fmaf(y0, wv.w, a0.w);
        a1.x = fmaf(y1, wv.x, a1.x); a1.y = fmaf(y1, wv.y, a1.y);
        a1.z = fmaf(y1, wv.z, a1.z); a1.w = fmaf(y1, wv.w, a1.w);
        a2.x = fmaf(y2, wv.x, a2.x); a2.y = fmaf(y2, wv.y, a2.y);
        a2.z = fmaf(y2, wv.z, a2.z); a2.w = fmaf(y2, wv.w, a2.w);
        a3.x = fmaf(y3, wv.x, a3.x); a3.y = fmaf(y3, wv.y, a3.y);
        a3.z = fmaf(y3, wv.z, a3.z); a3.w = fmaf(y3, wv.w, a3.w);
    }

    float4* Z4 = (float4*)Z_buf;
    const size_t r = (size_t)g0 + warp * 4;
    Z4[(r + 0) * 32 + lane] = a0;
    Z4[(r + 1) * 32 + lane] = a1;
    Z4[(r + 2) * 32 + lane] = a2;
    Z4[(r + 3) * 32 + lane] = a3;
}

// ---------------- row-per-lane top-4 scan + gather ----------------
// Block: 16 warps, 32 rows (one per lane, shared by all warps).
// Warp w scans slice [w*256, (w+1)*256) branch-free, keeping per-lane top-5
// smallest packed keys (d2 with low 12 mantissa bits = candidate index).
// Tree-merge across warps, exact difference-form rerank of top-5, gather Z.

#define GB_THREADS 512
#define GB_WARPS   16
#define SLICE      (N_PTS / GB_WARPS)      // 256
#define GB_ROWS    32

#define BUBBLE5(k)                                            \
    { float _t, _k = (k);                                     \
      _t = fminf(s0, _k); _k = fmaxf(s0, _k); s0 = _t;        \
      _t = fminf(s1, _k); _k = fmaxf(s1, _k); s1 = _t;        \
      _t = fminf(s2, _k); _k = fmaxf(s2, _k); s2 = _t;        \
      _t = fminf(s3, _k); _k = fmaxf(s3, _k); s3 = _t;        \
      s4 = fminf(s4, _k); }

#define SWP(a,b) { unsigned long long _t; if (a > b) { _t = a; a = b; b = _t; } }

__global__ void __launch_bounds__(GB_THREADS, 2)
topk_gather(const float* __restrict__ pos,
            const float* __restrict__ bias,
            float* __restrict__ out)
{
    extern __shared__ float smemB[];
    float4* pos_s = (float4*)smemB;                    // [4096] .w = -0.5*|p|^2
    float*  m_s   = (float*)(pos_s + N_PTS);           // [8*32*5] tree-merge staging
    float*  w_s   = m_s + 8 * 32 * 5;                  // [32*4] weights
    int*    idx_s = (int*)(w_s + 32 * 4);              // [32*4] indices

    const int tid  = threadIdx.x;
    const int warp = tid >> 5;
    const int lane = tid & 31;
    const int r0   = blockIdx.x * GB_ROWS;
    const int b    = r0 >> 12;
    const int n0   = r0 & (N_PTS - 1);

    // ---- load pos for this batch: 4 points per thread-iteration (3x float4) ----
    const float4* pb4 = (const float4*)(pos + (size_t)b * N_PTS * 3);
    for (int g = tid; g < N_PTS / 4; g += GB_THREADS) {
        float4 a = pb4[3*g + 0];
        float4 c = pb4[3*g + 1];
        float4 d = pb4[3*g + 2];
        float4 q;
        q.x = a.x; q.y = a.y; q.z = a.z;
        q.w = -0.5f * fmaf(q.z, q.z, fmaf(q.y, q.y, q.x * q.x));
        pos_s[4*g + 0] = q;
        q.x = a.w; q.y = c.x; q.z = c.y;
        q.w = -0.5f * fmaf(q.z, q.z, fmaf(q.y, q.y, q.x * q.x));
        pos_s[4*g + 1] = q;
        q.x = c.z; q.y = c.w; q.z = d.x;
        q.w = -0.5f * fmaf(q.z, q.z, fmaf(q.y, q.y, q.x * q.x));
        pos_s[4*g + 2] = q;
        q.x = d.y; q.y = d.z; q.z = d.w;
        q.w = -0.5f * fmaf(q.z, q.z, fmaf(q.y, q.y, q.x * q.x));
        pos_s[4*g + 3] = q;
    }
    __syncthreads();

    // ---- per-lane row state ----
    const float4 P   = pos_s[n0 + lane];
    const float  Pw2 = -2.0f * P.w;                    // |pi|^2

    const float INF = __int_as_float(0x7f800000);
    float s0 = INF, s1 = INF, s2 = INF, s3 = INF, s4 = INF;

    // ---- branch-free scan of this warp's slice ----
    const int base = warp * SLICE;
    #pragma unroll 4
    for (int jj = 0; jj < SLICE; jj++) {
        const int j = base + jj;
        float4 q = pos_s[j];                           // warp-broadcast LDS.128
        float t   = fmaf(P.x, q.x, fmaf(P.y, q.y, fmaf(P.z, q.z, q.w)));
        float d2c = fmaf(-2.0f, t, Pw2);               // ~squared distance
        float k   = __int_as_float((__float_as_int(d2c) & 0xFFFFF000) | j);
        BUBBLE5(k);                                    // unconditional, 9 FMNMX
    }

    // ---- tree merge across 16 warps (4 rounds) ----
    #pragma unroll
    for (int step = 8; step >= 1; step >>= 1) {
        if (warp >= step && warp < 2 * step) {
            float* m = m_s + ((warp - step) * 32 + lane) * 5;
            m[0] = s0; m[1] = s1; m[2] = s2; m[3] = s3; m[4] = s4;
        }
        __syncthreads();
        if (warp < step) {
            const float* m = m_s + (warp * 32 + lane) * 5;
            BUBBLE5(m[0]); BUBBLE5(m[1]); BUBBLE5(m[2]);
            BUBBLE5(m[3]); BUBBLE5(m[4]);
        }
        __syncthreads();
    }

    // ---- warp 0: exact rerank of the 5 survivors, weights + indices ----
    if (warp == 0) {
        float cand[5] = { s0, s1, s2, s3, s4 };
        unsigned long long k[5];
        #pragma unroll
        for (int i = 0; i < 5; i++) {
            int j = __float_as_int(cand[i]) & 0xFFF;
            float4 q = pos_s[j];
            float dx = P.x - q.x, dy = P.y - q.y, dz = P.z - q.z;
            float d2 = fmaf(dz, dz, fmaf(dy, dy, dx * dx));
            k[i] = ((unsigned long long)__float_as_uint(d2) << 32) | (unsigned)j;
        }
        SWP(k[0],k[1]) SWP(k[3],k[4]) SWP(k[2],k[4]) SWP(k[2],k[3]) SWP(k[0],k[3])
        SWP(k[0],k[2]) SWP(k[1],k[4]) SWP(k[1],k[3]) SWP(k[1],k[2])

        float wgt[TOPK];
        #pragma unroll
        for (int r = 0; r < TOPK; r++) {
            float d2 = __uint_as_float((unsigned)(k[r] >> 32));
            wgt[r]   = expf(-0.5f * (d2 + 1e-8f));
            idx_s[lane * TOPK + r] = (int)(k[r] & 0xFFFFFFFFull);
        }
        float inv = 1.0f / (((wgt[0] + wgt[1]) + wgt[2]) + wgt[3] + 1e-8f);
        #pragma unroll
        for (int r = 0; r < TOPK; r++) w_s[lane * TOPK + r] = wgt[r] * inv;
    }
    __syncthreads();

    // ---- gather: 16 warps x 2 rows; 32 lanes cover the 128 outputs ----
    const float4* Z4 = (const float4*)Z_buf + (size_t)b * N_PTS * 32;
    const float4  bv = ((const float4*)bias)[lane];
    float4* out4 = (float4*)out;

    #pragma unroll
    for (int rr = warp; rr < GB_ROWS; rr += GB_WARPS) {
        float w0 = w_s[rr*4+0], w1 = w_s[rr*4+1], w2 = w_s[rr*4+2], w3 = w_s[rr*4+3];
        int   i0 = idx_s[rr*4+0], i1 = idx_s[rr*4+1], i2 = idx_s[rr*4+2], i3 = idx_s[rr*4+3];
        float4 z0 = Z4[(size_t)i0 * 32 + lane];
        float4 z1 = Z4[(size_t)i1 * 32 + lane];
        float4 z2 = Z4[(size_t)i2 * 32 + lane];
        float4 z3 = Z4[(size_t)i3 * 32 + lane];
        float4 acc = bv;
        acc.x = fmaf(w0,z0.x, fmaf(w1,z1.x, fmaf(w2,z2.x, fmaf(w3,z3.x, acc.x))));
        acc.y = fmaf(w0,z0.y, fmaf(w1,z1.y, fmaf(w2,z2.y, fmaf(w3,z3.y, acc.y))));
        acc.z = fmaf(w0,z0.z, fmaf(w1,z1.z, fmaf(w2,z2.z, fmaf(w3,z3.z, acc.z))));
        acc.w = fmaf(w0,z0.w, fmaf(w1,z1.w, fmaf(w2,z2.w, fmaf(w3,z3.w, acc.w))));
        out4[(size_t)(r0 + rr) * 32 + lane] = acc;
    }
}

extern "C" void kernel_launch(void* const* d_in, const int* in_sizes, int n_in,
                              void* d_out, int out_size)
{
    const float* x    = (const float*)d_in[0];
    const float* pos  = (const float*)d_in[1];
    const float* W    = (const float*)d_in[2];
    const float* bias = (const float*)d_in[3];
    float* out        = (float*)d_out;

    const int rows = in_sizes[1] / 3;                  // B * N = 8192

    const size_t smemA = (size_t)DIM * 32 * 16 + (size_t)GA_ROWS * DIM * 4;  // 80 KB
    cudaFuncSetAttribute(gemm_xw, cudaFuncAttributeMaxDynamicSharedMemorySize, (int)smemA);
    gemm_xw<<<rows / GA_ROWS, GA_THREADS, smemA>>>(x, W);

    const size_t smemB = (size_t)N_PTS * 16            // pos_s
                       + 8 * 32 * 5 * 4                // tree-merge staging
                       + 32 * 4 * 4                    // weights
                       + 32 * 4 * 4;                   // indices
    cudaFuncSetAttribute(topk_gather, cudaFuncAttributeMaxDynamicSharedMemorySize, (int)smemB);
    topk_gather<<<rows / GB_ROWS, GB_THREADS, smemB>>>(pos, bias, out);
}

// round 6
// speedup vs baseline: 3.0089x; 1.1550x over previous
#include <cuda_runtime.h>
#include <cstdint>

#define N_PTS   4096
#define DIM     128
#define TOPK    4

// ---------------- Z = x @ W  (precomputed, 8192x128 @ 128x128) ----------------
__device__ float Z_buf[2 * N_PTS * DIM];   // 4 MB scratch

#define GA_THREADS 256
#define GA_ROWS    32          // rows per block; 8 warps x 4 rows

__global__ void __launch_bounds__(GA_THREADS, 2)
gemm_xw(const float* __restrict__ x, const float* __restrict__ W)
{
    extern __shared__ float smemA[];
    float4* W_s = (float4*)smemA;             // 128*32 float4 = 64 KB
    float*  x_s = (float*)(W_s + DIM * 32);   // 32*128 floats = 16 KB

    const int tid = threadIdx.x;
    const int g0  = blockIdx.x * GA_ROWS;

    const float4* W4 = (const float4*)W;
    #pragma unroll
    for (int i = tid; i < DIM * 32; i += GA_THREADS) W_s[i] = W4[i];

    const float4* xg = (const float4*)x + (size_t)g0 * 32;
    float4* xs4 = (float4*)x_s;
    #pragma unroll
    for (int i = tid; i < GA_ROWS * 32; i += GA_THREADS) xs4[i] = xg[i];
    __syncthreads();

    const int warp = tid >> 5;
    const int lane = tid & 31;
    const float* xr = x_s + warp * 4 * DIM;

    float4 a0 = make_float4(0.f,0.f,0.f,0.f);
    float4 a1 = a0, a2 = a0, a3 = a0;

    #pragma unroll 4
    for (int d = 0; d < DIM; d++) {
        float4 wv = W_s[d * 32 + lane];
        float y0 = xr[d];
        float y1 = xr[d + DIM];
        float y2 = xr[d + 2*DIM];
        float y3 = xr[d + 3*DIM];
        a0.x = fmaf(y0, wv.x, a0.x); a0.y = fmaf(y0, wv.y, a0.y);
        a0.z = fmaf(y0, wv.z, a0.z); a0.w = fmaf(y0, wv.w, a0.w);
        a1.x = fmaf(y1, wv.x, a1.x); a1.y = fmaf(y1, wv.y, a1.y);
        a1.z = fmaf(y1, wv.z, a1.z); a1.w = fmaf(y1, wv.w, a1.w);
        a2.x = fmaf(y2, wv.x, a2.x); a2.y = fmaf(y2, wv.y, a2.y);
        a2.z = fmaf(y2, wv.z, a2.z); a2.w = fmaf(y2, wv.w, a2.w);
        a3.x = fmaf(y3, wv.x, a3.x); a3.y = fmaf(y3, wv.y, a3.y);
        a3.z = fmaf(y3, wv.z, a3.z); a3.w = fmaf(y3, wv.w, a3.w);
    }

    float4* Z4 = (float4*)Z_buf;
    const size_t r = (size_t)g0 + warp * 4;
    Z4[(r + 0) * 32 + lane] = a0;
    Z4[(r + 1) * 32 + lane] = a1;
    Z4[(r + 2) * 32 + lane] = a2;
    Z4[(r + 3) * 32 + lane] = a3;
}

// ---------------- row-per-lane top-4 scan (filter-then-refine) + gather ----------------
// Block: 16 warps, 32 rows (one per lane, shared by all warps).
// Phase 1: each warp full-bubbles first 64 cands of its slice; tree-merge ->
//          block top-5 over 1024 samples -> per-row threshold tau.
// Phase 2: remaining 192 cands per slice with 1-FSETP filter; survivors bubbled.
// Final: tree-merge survivors + base-5, exact difference-form rerank, gather Z.

#define GB_THREADS 512
#define GB_WARPS   16
#define SLICE      (N_PTS / GB_WARPS)      // 256
#define L1SCAN     64                      // phase-1 candidates per warp
#define GB_ROWS    32

#define BUBBLE5(k)                                            \
    { float _t, _k = (k);                                     \
      _t = fminf(s0, _k); _k = fmaxf(s0, _k); s0 = _t;        \
      _t = fminf(s1, _k); _k = fmaxf(s1, _k); s1 = _t;        \
      _t = fminf(s2, _k); _k = fmaxf(s2, _k); s2 = _t;        \
      _t = fminf(s3, _k); _k = fmaxf(s3, _k); s3 = _t;        \
      s4 = fminf(s4, _k); }

// destructive tree-merge of per-warp (s0..s4) into warp 0
#define TREEMERGE()                                                        \
    _Pragma("unroll")                                                      \
    for (int step = 8; step >= 1; step >>= 1) {                            \
        if (warp >= step && warp < 2 * step) {                             \
            float* m = m_s + ((warp - step) * 32 + lane) * 5;              \
            m[0] = s0; m[1] = s1; m[2] = s2; m[3] = s3; m[4] = s4;         \
        }                                                                  \
        __syncthreads();                                                   \
        if (warp < step) {                                                 \
            const float* m = m_s + (warp * 32 + lane) * 5;                 \
            BUBBLE5(m[0]); BUBBLE5(m[1]); BUBBLE5(m[2]);                   \
            BUBBLE5(m[3]); BUBBLE5(m[4]);                                  \
        }                                                                  \
        __syncthreads();                                                   \
    }

#define SWP(a,b) { unsigned long long _t; if (a > b) { _t = a; a = b; b = _t; } }

__global__ void __launch_bounds__(GB_THREADS, 3)
topk_gather(const float* __restrict__ pos,
            const float* __restrict__ bias,
            float* __restrict__ out)
{
    extern __shared__ float smemB[];
    float4* pos_s  = (float4*)smemB;                   // [4096] .w = -0.5*|p|^2
    float*  m_s    = (float*)(pos_s + N_PTS);          // [8*32*5] tree-merge staging
    float*  base_s = m_s + 8 * 32 * 5;                 // [32*5] phase-1 block top-5
    float*  tau_s  = base_s + 32 * 5;                  // [32] thresholds
    float*  w_s    = tau_s + 32;                       // [32*4] weights
    int*    idx_s  = (int*)(w_s + 32 * 4);             // [32*4] indices

    const int tid  = threadIdx.x;
    const int warp = tid >> 5;
    const int lane = tid & 31;
    const int r0   = blockIdx.x * GB_ROWS;
    const int b    = r0 >> 12;
    const int n0   = r0 & (N_PTS - 1);

    // ---- load pos for this batch ----
    const float4* pb4 = (const float4*)(pos + (size_t)b * N_PTS * 3);
    for (int g = tid; g < N_PTS / 4; g += GB_THREADS) {
        float4 a = pb4[3*g + 0];
        float4 c = pb4[3*g + 1];
        float4 d = pb4[3*g + 2];
        float4 q;
        q.x = a.x; q.y = a.y; q.z = a.z;
        q.w = -0.5f * fmaf(q.z, q.z, fmaf(q.y, q.y, q.x * q.x));
        pos_s[4*g + 0] = q;
        q.x = a.w; q.y = c.x; q.z = c.y;
        q.w = -0.5f * fmaf(q.z, q.z, fmaf(q.y, q.y, q.x * q.x));
        pos_s[4*g + 1] = q;
        q.x = c.z; q.y = c.w; q.z = d.x;
        q.w = -0.5f * fmaf(q.z, q.z, fmaf(q.y, q.y, q.x * q.x));
        pos_s[4*g + 2] = q;
        q.x = d.y; q.y = d.z; q.z = d.w;
        q.w = -0.5f * fmaf(q.z, q.z, fmaf(q.y, q.y, q.x * q.x));
        pos_s[4*g + 3] = q;
    }
    __syncthreads();

    const float4 P   = pos_s[n0 + lane];
    const float  Pw2 = -2.0f * P.w;                    // |pi|^2

    const float INF = __int_as_float(0x7f800000);
    float s0 = INF, s1 = INF, s2 = INF, s3 = INF, s4 = INF;

    const int base = warp * SLICE;

    // ---- phase 1: unconditional bubble over first L1SCAN of the slice ----
    #pragma unroll 8
    for (int jj = 0; jj < L1SCAN; jj++) {
        const int j = base + jj;
        float4 q = pos_s[j];
        float t   = fmaf(P.x, q.x, fmaf(P.y, q.y, fmaf(P.z, q.z, q.w)));
        float d2c = fmaf(-2.0f, t, Pw2);
        float k   = __int_as_float((__float_as_int(d2c) & 0xFFFFF000) | j);
        BUBBLE5(k);
    }

    // ---- merge phase-1 results -> block top-5 of 1024 samples (in warp 0) ----
    TREEMERGE();

    if (warp == 0) {
        float* bs = base_s + lane * 5;
        bs[0] = s0; bs[1] = s1; bs[2] = s2; bs[3] = s3; bs[4] = s4;
        // threshold rounded up past the 12 index bits: no true candidate lost
        tau_s[lane] = __int_as_float((__float_as_int(s4) & 0xFFFFF000) + 0x1000);
    }
    __syncthreads();

    const float tau = tau_s[lane];

    // ---- phase 2: filtered scan of the rest of the slice ----
    s0 = INF; s1 = INF; s2 = INF; s3 = INF; s4 = INF;
    #pragma unroll 8
    for (int jj = L1SCAN; jj < SLICE; jj++) {
        const int j = base + jj;
        float4 q = pos_s[j];
        float t   = fmaf(P.x, q.x, fmaf(P.y, q.y, fmaf(P.z, q.z, q.w)));
        float d2c = fmaf(-2.0f, t, Pw2);
        if (d2c < tau) {                               // ~0.5% per lane
            float k = __int_as_float((__float_as_int(d2c) & 0xFFFFF000) | j);
            BUBBLE5(k);
        }
    }

    // ---- merge phase-2 survivors, fold in base-5, rerank exactly ----
    TREEMERGE();

    if (warp == 0) {
        const float* bs = base_s + lane * 5;
        BUBBLE5(bs[0]); BUBBLE5(bs[1]); BUBBLE5(bs[2]);
        BUBBLE5(bs[3]); BUBBLE5(bs[4]);

        float cand[5] = { s0, s1, s2, s3, s4 };
        unsigned long long k[5];
        #pragma unroll
        for (int i = 0; i < 5; i++) {
            int j = __float_as_int(cand[i]) & 0xFFF;
            float4 q = pos_s[j];
            float dx = P.x - q.x, dy = P.y - q.y, dz = P.z - q.z;
            float d2 = fmaf(dz, dz, fmaf(dy, dy, dx * dx));
            k[i] = ((unsigned long long)__float_as_uint(d2) << 32) | (unsigned)j;
        }
        SWP(k[0],k[1]) SWP(k[3],k[4]) SWP(k[2],k[4]) SWP(k[2],k[3]) SWP(k[0],k[3])
        SWP(k[0],k[2]) SWP(k[1],k[4]) SWP(k[1],k[3]) SWP(k[1],k[2])

        float wgt[TOPK];
        #pragma unroll
        for (int r = 0; r < TOPK; r++) {
            float d2 = __uint_as_float((unsigned)(k[r] >> 32));
            wgt[r]   = expf(-0.5f * (d2 + 1e-8f));
            idx_s[lane * TOPK + r] = (int)(k[r] & 0xFFFFFFFFull);
        }
        float inv = 1.0f / (((wgt[0] + wgt[1]) + wgt[2]) + wgt[3] + 1e-8f);
        #pragma unroll
        for (int r = 0; r < TOPK; r++) w_s[lane * TOPK + r] = wgt[r] * inv;
    }
    __syncthreads();

    // ---- gather: 16 warps x 2 rows; 32 lanes cover the 128 outputs ----
    const float4* Z4 = (const float4*)Z_buf + (size_t)b * N_PTS * 32;
    const float4  bv = ((const float4*)bias)[lane];
    float4* out4 = (float4*)out;

    #pragma unroll
    for (int rr = warp; rr < GB_ROWS; rr += GB_WARPS) {
        float w0 = w_s[rr*4+0], w1 = w_s[rr*4+1], w2 = w_s[rr*4+2], w3 = w_s[rr*4+3];
        int   i0 = idx_s[rr*4+0], i1 = idx_s[rr*4+1], i2 = idx_s[rr*4+2], i3 = idx_s[rr*4+3];
        float4 z0 = Z4[(size_t)i0 * 32 + lane];
        float4 z1 = Z4[(size_t)i1 * 32 + lane];
        float4 z2 = Z4[(size_t)i2 * 32 + lane];
        float4 z3 = Z4[(size_t)i3 * 32 + lane];
        float4 acc = bv;
        acc.x = fmaf(w0,z0.x, fmaf(w1,z1.x, fmaf(w2,z2.x, fmaf(w3,z3.x, acc.x))));
        acc.y = fmaf(w0,z0.y, fmaf(w1,z1.y, fmaf(w2,z2.y, fmaf(w3,z3.y, acc.y))));
        acc.z = fmaf(w0,z0.z, fmaf(w1,z1.z, fmaf(w2,z2.z, fmaf(w3,z3.z, acc.z))));
        acc.w = fmaf(w0,z0.w, fmaf(w1,z1.w, fmaf(w2,z2.w, fmaf(w3,z3.w, acc.w))));
        out4[(size_t)(r0 + rr) * 32 + lane] = acc;
    }
}

extern "C" void kernel_launch(void* const* d_in, const int* in_sizes, int n_in,
                              void* d_out, int out_size)
{
    const float* x    = (const float*)d_in[0];
    const float* pos  = (const float*)d_in[1];
    const float* W    = (const float*)d_in[2];
    const float* bias = (const float*)d_in[3];
    float* out        = (float*)d_out;

    const int rows = in_sizes[1] / 3;                  // B * N = 8192

    const size_t smemA = (size_t)DIM * 32 * 16 + (size_t)GA_ROWS * DIM * 4;  // 80 KB
    cudaFuncSetAttribute(gemm_xw, cudaFuncAttributeMaxDynamicSharedMemorySize, (int)smemA);
    gemm_xw<<<rows / GA_ROWS, GA_THREADS, smemA>>>(x, W);

    const size_t smemB = (size_t)N_PTS * 16            // pos_s        65536
                       + 8 * 32 * 5 * 4                // m_s           5120
                       + 32 * 5 * 4                    // base_s         640
                       + 32 * 4                        // tau_s          128
                       + 32 * 4 * 4                    // w_s            512
                       + 32 * 4 * 4;                   // idx_s          512
    cudaFuncSetAttribute(topk_gather, cudaFuncAttributeMaxDynamicSharedMemorySize, (int)smemB);
    topk_gather<<<rows / GB_ROWS, GB_THREADS, smemB>>>(pos, bias, out);
}